// round 15
// baseline (speedup 1.0000x reference)
#include <cuda_runtime.h>
#include <math.h>

#define NT 224

// shared weight bank for tiny middle stages
#define C3W 0
#define C3B 48
#define E1W 52
#define E1B 76
#define E2W 80
#define E2B 96
#define D1W 100
#define D1B 148
#define WTOT 152

#define NBAR(id, cnt) asm volatile("bar.sync %0, %1;" :: "r"(id), "r"(cnt) : "memory")

__device__ __forceinline__ float htanh(float x) {
    float y;
    asm("tanh.approx.f32 %0, %1;" : "=f"(y) : "f"(x));
    return y;
}

// fast atan2, ~1e-6 abs err (quaternion components, no 0/0 case)
__device__ __forceinline__ float fatan2(float y, float x) {
    float ax = fabsf(x), ay = fabsf(y);
    float mn = fminf(ax, ay), mx = fmaxf(ax, ay);
    float z = __fdividef(mn, mx);
    float z2 = z * z;
    float p = -0.0117212f;
    p = fmaf(p, z2,  0.05265332f);
    p = fmaf(p, z2, -0.11643287f);
    p = fmaf(p, z2,  0.19354346f);
    p = fmaf(p, z2, -0.33262347f);
    p = fmaf(p, z2,  0.99997726f);
    float a = p * z;
    if (ay > ax) a = 1.57079632679f - a;
    if (x < 0.0f) a = 3.14159265359f - a;
    return copysignf(a, y);
}

__global__ __launch_bounds__(NT, 1)
void conv_policy_kernel(const float* __restrict__ x,
                        const float* __restrict__ c1w, const float* __restrict__ c1b,
                        const float* __restrict__ c2w, const float* __restrict__ c2b,
                        const float* __restrict__ c3w, const float* __restrict__ c3b,
                        const float* __restrict__ e1w, const float* __restrict__ e1b,
                        const float* __restrict__ e2w, const float* __restrict__ e2b,
                        const float* __restrict__ d1w, const float* __restrict__ d1b,
                        const float* __restrict__ d2w, const float* __restrict__ d2b,
                        const float* __restrict__ d3w, const float* __restrict__ d3b,
                        const float* __restrict__ d4w, const float* __restrict__ d4b,
                        float* __restrict__ out)
{
    __shared__ float W[WTOT];
    // cat rows 0-1: dc3 (written by dec3); rows 2-13: jcat. cols 0,16 = zero pad.
    __shared__ float cat[14][17];
    __shared__ float fm1[6][14];    // col 13 pad (never read)

    const int t = threadIdx.x;

    // ===================== phase 0: one independent load wave ===============
    // psi inputs FIRST (lane 31): join the first LDG batch so the fatan2
    // chain starts as early as possible (result consumed only after NBAR1)
    float psi_v = 0.0f, obsd_v = 0.0f;
    if (t == 31) {
        float qw = x[3], qx = x[4], qy = x[5], qz = x[6];
        float ob = x[100];
        psi_v  = fatan2(qz, qw) - fatan2(-qx, qy);
        obsd_v = ob;
    }
    if (t < 180) {
        int c = t / 15, l = t % 15;
        float v;
        if (c < 6) {
            int j = c * 15 + l;
            v = (j < 2) ? 0.0f : x[7 + j - 2];
        } else {
            int j = (c - 6) * 15 + l;
            v = (j < 2) ? 0.0f : x[101 + j - 2];
        }
        cat[2 + c][1 + l] = v;
    }
    if (t >= 180 && t < 208) {
        int r = (t - 180) >> 1, c = (t & 1) ? 16 : 0;
        cat[r][c] = 0.0f;
    }

    // conv1 weights -> regs on warps 1-3 (threads 32..109): 9x LDG.128
    float w1[36], b1 = 0.0f;
    int o1 = 0, l1 = 0;
    const bool is_c1 = (t >= 32 && t < 110);
    if (is_c1) {
        int u = t - 32;
        o1 = u / 13; l1 = u % 13;
        const float4* c1w4 = reinterpret_cast<const float4*>(c1w + o1 * 36);
        #pragma unroll
        for (int i = 0; i < 9; i++) {
            float4 q = c1w4[i];
            w1[i * 4 + 0] = q.x; w1[i * 4 + 1] = q.y;
            w1[i * 4 + 2] = q.z; w1[i * 4 + 3] = q.w;
        }
        b1 = c1b[o1];
    }
    // dec4 weights -> regs on warps 4-6 (threads 128..215)
    float w4[42], b4 = 0.0f;
    int o4 = 0, l4 = 0;
    const bool is_d4 = (t >= 128 && t < 216);
    if (is_d4) {
        int g = (t - 128) + 2; o4 = g / 15; l4 = g % 15;
        #pragma unroll
        for (int i = 0; i < 14; i++)
            #pragma unroll
            for (int h = 0; h < 3; h++)
                w4[i * 3 + h] = d4w[i * 18 + o4 * 3 + h];
        b4 = d4b[o4];
    }
    // warp-0 per-lane middle weights (preselected / zero-masked)
    float wc2[19];          // conv2 (lanes 0..11)
    if (t < 12) {
        int o = t / 3;
        const float2* c2w2 = reinterpret_cast<const float2*>(c2w + o * 18);
        #pragma unroll
        for (int i = 0; i < 9; i++) {
            float2 q = c2w2[i];
            wc2[i * 2 + 0] = q.x; wc2[i * 2 + 1] = q.y;
        }
        wc2[18] = c2b[o];
    }
    float wd2[13];          // dec2 (lanes 0..9)
    if (t < 10) {
        int o = t / 5, l = t % 5;
        #pragma unroll
        for (int i = 0; i < 4; i++)
            #pragma unroll
            for (int p = 0; p < 3; p++) {
                int h = l - p;
                wd2[i * 3 + p] = (h >= 0 && h < 3) ? d2w[(i * 2 + o) * 3 + h] : 0.0f;
            }
        wd2[12] = d2b[o];
    }
    float wd3[7];           // dec3 (lanes 0..29)
    if (t < 30) {
        int o = t / 15, l = t % 15;
        #pragma unroll
        for (int i = 0; i < 2; i++)
            #pragma unroll
            for (int h = 0; h < 3; h++) {
                int p = l - h;
                wd3[i * 3 + h] = (p >= 0 && p < 13) ? d3w[(i * 2 + o) * 3 + h] : 0.0f;
            }
        wd3[6] = d3b[o];
    }
    // shared bank for remaining tiny stages (loaded by warps 1-6)
    if (t >= 32) {
        int u = t - 32;  // 0..191
        #define CP(off, src, n) for (int i = u; i < (n); i += 192) W[(off) + i] = (src)[i];
        CP(C3W, c3w, 48)  CP(C3B, c3b, 4)
        CP(E1W, e1w, 24)  CP(E1B, e1b, 4)
        CP(E2W, e2w, 16)  CP(E2B, e2b, 4)
        CP(D1W, d1w, 48)  CP(D1B, d1b, 4)
        #undef CP
    }
    __syncthreads();   // ---- b1: jcat + W bank ready ----

    if (t < 32) {
        // ======== warp 0: prefetch middle weights (hidden under conv1) ======
        const int oc = t & 3;
        const int rd = (t < 12) ? t : 0;
        const int od = rd / 3, ld = rd % 3;
        float wc3[12], we1[6], we2[4], wd1[4];
        #pragma unroll
        for (int i = 0; i < 4; i++)
            #pragma unroll
            for (int h = 0; h < 3; h++)
                wc3[i * 3 + h] = W[C3W + (oc * 4 + i) * 3 + h];
        float bc3 = W[C3B + oc];
        #pragma unroll
        for (int i = 0; i < 6; i++) we1[i] = W[E1W + oc * 6 + i];
        float be1 = W[E1B + oc];
        #pragma unroll
        for (int i = 0; i < 4; i++) we2[i] = W[E2W + oc * 4 + i];
        float be2 = W[E2B + oc];
        #pragma unroll
        for (int i = 0; i < 4; i++) wd1[i] = W[D1W + (i * 4 + od) * 3 + ld];
        float bd1 = W[D1B + od];

        NBAR(1, 128);   // ---- fm1 ready (warp 0 + warps 1-3) ----

        // ======== middle: register-resident, shuffle-chained ================
        const unsigned FULL = 0xffffffffu;

        // pool 13 -> 5 (lanes 0..29: o*5+p)
        int rr = (t < 30) ? t : 0;
        int po = rr / 5, pp = rr % 5;
        int S = (pp * 13) / 5;
        int sz4 = (((pp + 1) * 13 + 4) / 5 - S) == 4;
        float v3 = fm1[po][S + 3];
        float vp = fm1[po][S] + fm1[po][S + 1] + fm1[po][S + 2] + (sz4 ? v3 : 0.0f);
        vp *= sz4 ? 0.25f : (1.0f / 3.0f);

        // conv2 (lanes 0..11)
        int r2 = (t < 12) ? t : 0;
        int l2 = r2 % 3;
        float a0 = wc2[18], a1 = 0.0f;
        #pragma unroll
        for (int i = 0; i < 6; i++) {
            float v0 = __shfl_sync(FULL, vp, i * 5 + l2 + 0);
            float v1 = __shfl_sync(FULL, vp, i * 5 + l2 + 1);
            float v2 = __shfl_sync(FULL, vp, i * 5 + l2 + 2);
            a0 = fmaf(wc2[i * 3 + 0], v0, a0);
            a1 = fmaf(wc2[i * 3 + 1], v1, a1);
            a0 = fmaf(wc2[i * 3 + 2], v2, a0);
        }
        float fm2v = htanh(a0 + a1);

        // conv3 (lanes 0..3)
        float c0 = bc3, c1 = 0.0f;
        #pragma unroll
        for (int i = 0; i < 4; i++)
            #pragma unroll
            for (int h = 0; h < 3; h++) {
                float v = __shfl_sync(FULL, fm2v, i * 3 + h);
                if (h & 1) c1 = fmaf(wc3[i * 3 + h], v, c1);
                else       c0 = fmaf(wc3[i * 3 + h], v, c0);
            }
        float c3v = htanh(c0 + c1);

        // emb1 (lanes 0..3, 6->4); psi/obsd shuffled from lane 31
        float psi_b  = __shfl_sync(FULL, psi_v, 31);
        float obsd_b = __shfl_sync(FULL, obsd_v, 31);
        float e0 = be1, e1a = 0.0f;
        #pragma unroll
        for (int i = 0; i < 4; i++) {
            float v = __shfl_sync(FULL, c3v, i);
            if (i & 1) e1a = fmaf(we1[i], v, e1a);
            else       e0  = fmaf(we1[i], v, e0);
        }
        e0  = fmaf(we1[4], psi_b, e0);
        e1a = fmaf(we1[5], obsd_b, e1a);
        float e1v = htanh(e0 + e1a);

        // emb2 (lanes 0..3, 4->4)
        float f0 = be2, f1 = 0.0f;
        #pragma unroll
        for (int i = 0; i < 4; i++) {
            float v = __shfl_sync(FULL, e1v, i);
            if (i & 1) f1 = fmaf(we2[i], v, f1);
            else       f0 = fmaf(we2[i], v, f0);
        }
        float e2v = htanh(f0 + f1);

        // dec1 (lanes 0..11)
        float g0 = bd1, g1 = 0.0f;
        #pragma unroll
        for (int i = 0; i < 4; i++) {
            float v = __shfl_sync(FULL, e2v, i);
            if (i & 1) g1 = fmaf(wd1[i], v, g1);
            else       g0 = fmaf(wd1[i], v, g0);
        }
        float d1v = htanh(g0 + g1);

        // dec2 (lanes 0..9)
        float h0 = wd2[12], h1 = 0.0f;
        #pragma unroll
        for (int i = 0; i < 4; i++)
            #pragma unroll
            for (int p = 0; p < 3; p++) {
                float v = __shfl_sync(FULL, d1v, i * 3 + p);
                if (p & 1) h1 = fmaf(wd2[i * 3 + p], v, h1);
                else       h0 = fmaf(wd2[i * 3 + p], v, h0);
            }
        float d2v = htanh(h0 + h1);

        // dec3 + fused upsample (lanes 0..29) -> cat rows 0,1
        int r3 = (t < 30) ? t : 0;
        int o3 = r3 / 15, l3 = r3 % 15;
        float k0 = wd3[6], k1 = 0.0f;
        #pragma unroll
        for (int i = 0; i < 2; i++)
            #pragma unroll
            for (int h = 0; h < 3; h++) {
                int p = l3 - h;
                int pc = p < 0 ? 0 : (p > 12 ? 12 : p);
                int q = (pc * 5) / 13;                 // UP_IDX
                float v = __shfl_sync(FULL, d2v, i * 5 + q);
                if (h & 1) k1 = fmaf(wd3[i * 3 + h], v, k1);
                else       k0 = fmaf(wd3[i * 3 + h], v, k0);
            }
        if (t < 30) cat[o3][1 + l3] = htanh(k0 + k1);

        NBAR(2, 128);   // ---- dc3 ready (warp 0 + warps 4-6) ----
    } else if (t < 128) {
        // ======== warps 1-3: conv1 (12,15) k=3 -> (6,13), tanh ==============
        if (is_c1) {
            float s0 = b1, s1 = 0.0f, s2 = 0.0f;
            #pragma unroll
            for (int i = 0; i < 12; i++) {
                s0 = fmaf(w1[i * 3 + 0], cat[2 + i][1 + l1 + 0], s0);
                s1 = fmaf(w1[i * 3 + 1], cat[2 + i][1 + l1 + 1], s1);
                s2 = fmaf(w1[i * 3 + 2], cat[2 + i][1 + l1 + 2], s2);
            }
            fm1[o1][l1] = htanh(s0 + s1 + s2);
        }
        NBAR(1, 128);   // fm1 ready
    } else {
        // ======== warps 4-6: dec4 jcat-partial, then wait for dc3 ===========
        float partial = 0.0f;
        if (is_d4) {
            float s0 = b4, s1 = 0.0f, s2 = 0.0f;
            #pragma unroll
            for (int h = 0; h < 3; h++) {
                int p = l4 - h + 2;   // [0..16], pads zero
                #pragma unroll
                for (int i = 2; i < 14; i++) {
                    float v = cat[i][p];
                    if (i % 3 == 0)      s0 = fmaf(w4[i * 3 + h], v, s0);
                    else if (i % 3 == 1) s1 = fmaf(w4[i * 3 + h], v, s1);
                    else                 s2 = fmaf(w4[i * 3 + h], v, s2);
                }
            }
            partial = s0 + s1 + s2;
        }
        NBAR(2, 128);   // dc3 ready

        if (is_d4) {
            float s = partial;
            #pragma unroll
            for (int h = 0; h < 3; h++) {
                int p = l4 - h + 2;
                s = fmaf(w4[0 * 3 + h], cat[0][p], s);
                s = fmaf(w4[1 * 3 + h], cat[1][p], s);
            }
            out[t - 128] = s;
        }
    }
}

extern "C" void kernel_launch(void* const* d_in, const int* in_sizes, int n_in,
                              void* d_out, int out_size) {
    (void)in_sizes; (void)n_in; (void)out_size;
    conv_policy_kernel<<<1, NT>>>(
        (const float*)d_in[0],
        (const float*)d_in[1],  (const float*)d_in[2],
        (const float*)d_in[3],  (const float*)d_in[4],
        (const float*)d_in[5],  (const float*)d_in[6],
        (const float*)d_in[7],  (const float*)d_in[8],
        (const float*)d_in[9],  (const float*)d_in[10],
        (const float*)d_in[11], (const float*)d_in[12],
        (const float*)d_in[13], (const float*)d_in[14],
        (const float*)d_in[15], (const float*)d_in[16],
        (const float*)d_in[17], (const float*)d_in[18],
        (float*)d_out);
}

// round 16
// speedup vs baseline: 1.0049x; 1.0049x over previous
#include <cuda_runtime.h>
#include <math.h>

#define NT 224

// shared weight bank for tiny middle stages
#define C3W 0
#define C3B 48
#define E1W 52
#define E1B 76
#define E2W 80
#define E2B 96
#define D1W 100
#define D1B 148
#define WTOT 152

#define NBAR(id, cnt) asm volatile("bar.sync %0, %1;" :: "r"(id), "r"(cnt) : "memory")

__device__ __forceinline__ float htanh(float x) {
    float y;
    asm("tanh.approx.f32 %0, %1;" : "=f"(y) : "f"(x));
    return y;
}

// fast atan2, ~1e-6 abs err (quaternion components, no 0/0 case)
__device__ __forceinline__ float fatan2(float y, float x) {
    float ax = fabsf(x), ay = fabsf(y);
    float mn = fminf(ax, ay), mx = fmaxf(ax, ay);
    float z = __fdividef(mn, mx);
    float z2 = z * z;
    float p = -0.0117212f;
    p = fmaf(p, z2,  0.05265332f);
    p = fmaf(p, z2, -0.11643287f);
    p = fmaf(p, z2,  0.19354346f);
    p = fmaf(p, z2, -0.33262347f);
    p = fmaf(p, z2,  0.99997726f);
    float a = p * z;
    if (ay > ax) a = 1.57079632679f - a;
    if (x < 0.0f) a = 3.14159265359f - a;
    return copysignf(a, y);
}

__global__ __launch_bounds__(NT, 1)
void conv_policy_kernel(const float* __restrict__ x,
                        const float* __restrict__ c1w, const float* __restrict__ c1b,
                        const float* __restrict__ c2w, const float* __restrict__ c2b,
                        const float* __restrict__ c3w, const float* __restrict__ c3b,
                        const float* __restrict__ e1w, const float* __restrict__ e1b,
                        const float* __restrict__ e2w, const float* __restrict__ e2b,
                        const float* __restrict__ d1w, const float* __restrict__ d1b,
                        const float* __restrict__ d2w, const float* __restrict__ d2b,
                        const float* __restrict__ d3w, const float* __restrict__ d3b,
                        const float* __restrict__ d4w, const float* __restrict__ d4b,
                        float* __restrict__ out)
{
    __shared__ float W[WTOT];
    // cat rows 0-1: dc3 (written by dec3); rows 2-13: jcat. cols 0,16 = zero pad.
    __shared__ float cat[14][17];
    __shared__ float fm1[6][14];    // col 13 pad (never read)

    const int t = threadIdx.x;

    // ===================== phase 0: one independent load wave ===============
    if (t < 180) {
        int c = t / 15, l = t % 15;
        float v;
        if (c < 6) {
            int j = c * 15 + l;
            v = (j < 2) ? 0.0f : x[7 + j - 2];
        } else {
            int j = (c - 6) * 15 + l;
            v = (j < 2) ? 0.0f : x[101 + j - 2];
        }
        cat[2 + c][1 + l] = v;
    }
    if (t >= 180 && t < 208) {
        int r = (t - 180) >> 1, c = (t & 1) ? 16 : 0;
        cat[r][c] = 0.0f;
    }

    // conv1 weights -> regs on warps 1-3 (threads 32..109): 9x LDG.128
    float w1[36], b1 = 0.0f;
    int o1 = 0, l1 = 0;
    const bool is_c1 = (t >= 32 && t < 110);
    if (is_c1) {
        int u = t - 32;
        o1 = u / 13; l1 = u % 13;
        const float4* c1w4 = reinterpret_cast<const float4*>(c1w + o1 * 36);
        #pragma unroll
        for (int i = 0; i < 9; i++) {
            float4 q = c1w4[i];
            w1[i * 4 + 0] = q.x; w1[i * 4 + 1] = q.y;
            w1[i * 4 + 2] = q.z; w1[i * 4 + 3] = q.w;
        }
        b1 = c1b[o1];
    }
    // dec4 weights -> regs on warps 4-6 (threads 128..215)
    float w4[42], b4 = 0.0f;
    int o4 = 0, l4 = 0;
    const bool is_d4 = (t >= 128 && t < 216);
    if (is_d4) {
        int g = (t - 128) + 2; o4 = g / 15; l4 = g % 15;
        #pragma unroll
        for (int i = 0; i < 14; i++)
            #pragma unroll
            for (int h = 0; h < 3; h++)
                w4[i * 3 + h] = d4w[i * 18 + o4 * 3 + h];
        b4 = d4b[o4];
    }
    // warp-0 per-lane middle weights (preselected / zero-masked)
    float wc2[19];          // conv2 (lanes 0..11)
    if (t < 12) {
        int o = t / 3;
        const float2* c2w2 = reinterpret_cast<const float2*>(c2w + o * 18);
        #pragma unroll
        for (int i = 0; i < 9; i++) {
            float2 q = c2w2[i];
            wc2[i * 2 + 0] = q.x; wc2[i * 2 + 1] = q.y;
        }
        wc2[18] = c2b[o];
    }
    float wd2[13];          // dec2 (lanes 0..9)
    if (t < 10) {
        int o = t / 5, l = t % 5;
        #pragma unroll
        for (int i = 0; i < 4; i++)
            #pragma unroll
            for (int p = 0; p < 3; p++) {
                int h = l - p;
                wd2[i * 3 + p] = (h >= 0 && h < 3) ? d2w[(i * 2 + o) * 3 + h] : 0.0f;
            }
        wd2[12] = d2b[o];
    }
    float wd3[7];           // dec3 (lanes 0..29)
    if (t < 30) {
        int o = t / 15, l = t % 15;
        #pragma unroll
        for (int i = 0; i < 2; i++)
            #pragma unroll
            for (int h = 0; h < 3; h++) {
                int p = l - h;
                wd3[i * 3 + h] = (p >= 0 && p < 13) ? d3w[(i * 2 + o) * 3 + h] : 0.0f;
            }
        wd3[6] = d3b[o];
    }
    // psi + obsd tail on warp-0 lane 31 (hidden under warp 0's NBAR1 wait)
    float psi_v = 0.0f, obsd_v = 0.0f;
    if (t == 31) {
        float qw = x[3], qx = x[4], qy = x[5], qz = x[6];
        psi_v  = fatan2(qz, qw) - fatan2(-qx, qy);
        obsd_v = x[100];
    }
    // shared bank for remaining tiny stages (loaded by warps 1-6)
    if (t >= 32) {
        int u = t - 32;  // 0..191
        #define CP(off, src, n) for (int i = u; i < (n); i += 192) W[(off) + i] = (src)[i];
        CP(C3W, c3w, 48)  CP(C3B, c3b, 4)
        CP(E1W, e1w, 24)  CP(E1B, e1b, 4)
        CP(E2W, e2w, 16)  CP(E2B, e2b, 4)
        CP(D1W, d1w, 48)  CP(D1B, d1b, 4)
        #undef CP
    }
    __syncthreads();   // ---- b1: jcat + W bank ready ----

    if (t < 32) {
        // ======== warp 0: prefetch middle weights (hidden under conv1) ======
        const int oc = t & 3;
        const int rd = (t < 12) ? t : 0;
        const int od = rd / 3, ld = rd % 3;
        float wc3[12], we1[6], we2[4], wd1[4];
        #pragma unroll
        for (int i = 0; i < 4; i++)
            #pragma unroll
            for (int h = 0; h < 3; h++)
                wc3[i * 3 + h] = W[C3W + (oc * 4 + i) * 3 + h];
        float bc3 = W[C3B + oc];
        #pragma unroll
        for (int i = 0; i < 6; i++) we1[i] = W[E1W + oc * 6 + i];
        float be1 = W[E1B + oc];
        #pragma unroll
        for (int i = 0; i < 4; i++) we2[i] = W[E2W + oc * 4 + i];
        float be2 = W[E2B + oc];
        #pragma unroll
        for (int i = 0; i < 4; i++) wd1[i] = W[D1W + (i * 4 + od) * 3 + ld];
        float bd1 = W[D1B + od];

        NBAR(1, 128);   // ---- fm1 ready (warp 0 + warps 1-3) ----

        // ======== middle: register-resident, shuffle-chained ================
        const unsigned FULL = 0xffffffffu;

        // pool 13 -> 5 (lanes 0..29: o*5+p)
        int rr = (t < 30) ? t : 0;
        int po = rr / 5, pp = rr % 5;
        int S = (pp * 13) / 5;
        int sz4 = (((pp + 1) * 13 + 4) / 5 - S) == 4;
        float v3 = fm1[po][S + 3];
        float vp = fm1[po][S] + fm1[po][S + 1] + fm1[po][S + 2] + (sz4 ? v3 : 0.0f);
        vp *= sz4 ? 0.25f : (1.0f / 3.0f);

        // conv2 (lanes 0..11)
        int r2 = (t < 12) ? t : 0;
        int l2 = r2 % 3;
        float a0 = wc2[18], a1 = 0.0f;
        #pragma unroll
        for (int i = 0; i < 6; i++) {
            float v0 = __shfl_sync(FULL, vp, i * 5 + l2 + 0);
            float v1 = __shfl_sync(FULL, vp, i * 5 + l2 + 1);
            float v2 = __shfl_sync(FULL, vp, i * 5 + l2 + 2);
            a0 = fmaf(wc2[i * 3 + 0], v0, a0);
            a1 = fmaf(wc2[i * 3 + 1], v1, a1);
            a0 = fmaf(wc2[i * 3 + 2], v2, a0);
        }
        float fm2v = htanh(a0 + a1);

        // conv3 (lanes 0..3)
        float c0 = bc3, c1 = 0.0f;
        #pragma unroll
        for (int i = 0; i < 4; i++)
            #pragma unroll
            for (int h = 0; h < 3; h++) {
                float v = __shfl_sync(FULL, fm2v, i * 3 + h);
                if (h & 1) c1 = fmaf(wc3[i * 3 + h], v, c1);
                else       c0 = fmaf(wc3[i * 3 + h], v, c0);
            }
        float c3v = htanh(c0 + c1);

        // emb1 (lanes 0..3, 6->4); psi/obsd shuffled from lane 31
        float psi_b  = __shfl_sync(FULL, psi_v, 31);
        float obsd_b = __shfl_sync(FULL, obsd_v, 31);
        float e0 = be1, e1a = 0.0f;
        #pragma unroll
        for (int i = 0; i < 4; i++) {
            float v = __shfl_sync(FULL, c3v, i);
            if (i & 1) e1a = fmaf(we1[i], v, e1a);
            else       e0  = fmaf(we1[i], v, e0);
        }
        e0  = fmaf(we1[4], psi_b, e0);
        e1a = fmaf(we1[5], obsd_b, e1a);
        float e1v = htanh(e0 + e1a);

        // emb2 (lanes 0..3, 4->4)
        float f0 = be2, f1 = 0.0f;
        #pragma unroll
        for (int i = 0; i < 4; i++) {
            float v = __shfl_sync(FULL, e1v, i);
            if (i & 1) f1 = fmaf(we2[i], v, f1);
            else       f0 = fmaf(we2[i], v, f0);
        }
        float e2v = htanh(f0 + f1);

        // dec1 (lanes 0..11)
        float g0 = bd1, g1 = 0.0f;
        #pragma unroll
        for (int i = 0; i < 4; i++) {
            float v = __shfl_sync(FULL, e2v, i);
            if (i & 1) g1 = fmaf(wd1[i], v, g1);
            else       g0 = fmaf(wd1[i], v, g0);
        }
        float d1v = htanh(g0 + g1);

        // dec2 (lanes 0..9)
        float h0 = wd2[12], h1 = 0.0f;
        #pragma unroll
        for (int i = 0; i < 4; i++)
            #pragma unroll
            for (int p = 0; p < 3; p++) {
                float v = __shfl_sync(FULL, d1v, i * 3 + p);
                if (p & 1) h1 = fmaf(wd2[i * 3 + p], v, h1);
                else       h0 = fmaf(wd2[i * 3 + p], v, h0);
            }
        float d2v = htanh(h0 + h1);

        // dec3 + fused upsample (lanes 0..29) -> cat rows 0,1
        int r3 = (t < 30) ? t : 0;
        int o3 = r3 / 15, l3 = r3 % 15;
        float k0 = wd3[6], k1 = 0.0f;
        #pragma unroll
        for (int i = 0; i < 2; i++)
            #pragma unroll
            for (int h = 0; h < 3; h++) {
                int p = l3 - h;
                int pc = p < 0 ? 0 : (p > 12 ? 12 : p);
                int q = (pc * 5) / 13;                 // UP_IDX
                float v = __shfl_sync(FULL, d2v, i * 5 + q);
                if (h & 1) k1 = fmaf(wd3[i * 3 + h], v, k1);
                else       k0 = fmaf(wd3[i * 3 + h], v, k0);
            }
        if (t < 30) cat[o3][1 + l3] = htanh(k0 + k1);

        NBAR(2, 128);   // ---- dc3 ready (warp 0 + warps 4-6) ----
    } else if (t < 128) {
        // ======== warps 1-3: conv1 (12,15) k=3 -> (6,13), tanh ==============
        if (is_c1) {
            float s0 = b1, s1 = 0.0f, s2 = 0.0f;
            #pragma unroll
            for (int i = 0; i < 12; i++) {
                s0 = fmaf(w1[i * 3 + 0], cat[2 + i][1 + l1 + 0], s0);
                s1 = fmaf(w1[i * 3 + 1], cat[2 + i][1 + l1 + 1], s1);
                s2 = fmaf(w1[i * 3 + 2], cat[2 + i][1 + l1 + 2], s2);
            }
            fm1[o1][l1] = htanh(s0 + s1 + s2);
        }
        NBAR(1, 128);   // fm1 ready
    } else {
        // ======== warps 4-6: dec4 jcat-partial, then wait for dc3 ===========
        float partial = 0.0f;
        if (is_d4) {
            float s0 = b4, s1 = 0.0f, s2 = 0.0f;
            #pragma unroll
            for (int h = 0; h < 3; h++) {
                int p = l4 - h + 2;   // [0..16], pads zero
                #pragma unroll
                for (int i = 2; i < 14; i++) {
                    float v = cat[i][p];
                    if (i % 3 == 0)      s0 = fmaf(w4[i * 3 + h], v, s0);
                    else if (i % 3 == 1) s1 = fmaf(w4[i * 3 + h], v, s1);
                    else                 s2 = fmaf(w4[i * 3 + h], v, s2);
                }
            }
            partial = s0 + s1 + s2;
        }
        NBAR(2, 128);   // dc3 ready

        if (is_d4) {
            float s = partial;
            #pragma unroll
            for (int h = 0; h < 3; h++) {
                int p = l4 - h + 2;
                s = fmaf(w4[0 * 3 + h], cat[0][p], s);
                s = fmaf(w4[1 * 3 + h], cat[1][p], s);
            }
            out[t - 128] = s;
        }
    }
}

extern "C" void kernel_launch(void* const* d_in, const int* in_sizes, int n_in,
                              void* d_out, int out_size) {
    (void)in_sizes; (void)n_in; (void)out_size;
    conv_policy_kernel<<<1, NT>>>(
        (const float*)d_in[0],
        (const float*)d_in[1],  (const float*)d_in[2],
        (const float*)d_in[3],  (const float*)d_in[4],
        (const float*)d_in[5],  (const float*)d_in[6],
        (const float*)d_in[7],  (const float*)d_in[8],
        (const float*)d_in[9],  (const float*)d_in[10],
        (const float*)d_in[11], (const float*)d_in[12],
        (const float*)d_in[13], (const float*)d_in[14],
        (const float*)d_in[15], (const float*)d_in[16],
        (const float*)d_in[17], (const float*)d_in[18],
        (float*)d_out);
}

// round 17
// speedup vs baseline: 1.0670x; 1.0619x over previous
#include <cuda_runtime.h>
#include <math.h>

#define NT 224

// shared weight bank for tiny middle stages
#define C3W 0
#define C3B 48
#define E1W 52
#define E1B 76
#define E2W 80
#define E2B 96
#define D1W 100
#define D1B 148
#define WTOT 152

#define NBAR(id, cnt) asm volatile("bar.sync %0, %1;" :: "r"(id), "r"(cnt) : "memory")

__device__ __forceinline__ float htanh(float x) {
    float y;
    asm("tanh.approx.f32 %0, %1;" : "=f"(y) : "f"(x));
    return y;
}

// fast atan2, ~1e-6 abs err (quaternion components, no 0/0 case)
__device__ __forceinline__ float fatan2(float y, float x) {
    float ax = fabsf(x), ay = fabsf(y);
    float mn = fminf(ax, ay), mx = fmaxf(ax, ay);
    float z = __fdividef(mn, mx);
    float z2 = z * z;
    float p = -0.0117212f;
    p = fmaf(p, z2,  0.05265332f);
    p = fmaf(p, z2, -0.11643287f);
    p = fmaf(p, z2,  0.19354346f);
    p = fmaf(p, z2, -0.33262347f);
    p = fmaf(p, z2,  0.99997726f);
    float a = p * z;
    if (ay > ax) a = 1.57079632679f - a;
    if (x < 0.0f) a = 3.14159265359f - a;
    return copysignf(a, y);
}

__global__ __launch_bounds__(NT, 1)
void conv_policy_kernel(const float* __restrict__ x,
                        const float* __restrict__ c1w, const float* __restrict__ c1b,
                        const float* __restrict__ c2w, const float* __restrict__ c2b,
                        const float* __restrict__ c3w, const float* __restrict__ c3b,
                        const float* __restrict__ e1w, const float* __restrict__ e1b,
                        const float* __restrict__ e2w, const float* __restrict__ e2b,
                        const float* __restrict__ d1w, const float* __restrict__ d1b,
                        const float* __restrict__ d2w, const float* __restrict__ d2b,
                        const float* __restrict__ d3w, const float* __restrict__ d3b,
                        const float* __restrict__ d4w, const float* __restrict__ d4b,
                        float* __restrict__ out)
{
    __shared__ float W[WTOT];
    // cat rows 0-1: dc3 (written by dec3); rows 2-13: jcat. cols 0,16 = zero pad.
    __shared__ float cat[14][17];
    __shared__ float fm1[6][14];    // col 13 pad (never read)

    const int t = threadIdx.x;

    // ===================== phase 0: one independent load wave ===============
    if (t < 180) {
        int c = t / 15, l = t % 15;
        float v;
        if (c < 6) {
            int j = c * 15 + l;
            v = (j < 2) ? 0.0f : x[7 + j - 2];
        } else {
            int j = (c - 6) * 15 + l;
            v = (j < 2) ? 0.0f : x[101 + j - 2];
        }
        cat[2 + c][1 + l] = v;
    }
    if (t >= 180 && t < 208) {
        int r = (t - 180) >> 1, c = (t & 1) ? 16 : 0;
        cat[r][c] = 0.0f;
    }

    // conv1 weights -> regs on warps 1-3 (threads 32..109): 9x LDG.128
    float w1[36], b1 = 0.0f;
    int o1 = 0, l1 = 0;
    const bool is_c1 = (t >= 32 && t < 110);
    if (is_c1) {
        int u = t - 32;
        o1 = u / 13; l1 = u % 13;
        const float4* c1w4 = reinterpret_cast<const float4*>(c1w + o1 * 36);
        #pragma unroll
        for (int i = 0; i < 9; i++) {
            float4 q = c1w4[i];
            w1[i * 4 + 0] = q.x; w1[i * 4 + 1] = q.y;
            w1[i * 4 + 2] = q.z; w1[i * 4 + 3] = q.w;
        }
        b1 = c1b[o1];
    }
    // dec4 weights -> regs on warps 4-6 (threads 128..215)
    float w4[42], b4 = 0.0f;
    int o4 = 0, l4 = 0;
    const bool is_d4 = (t >= 128 && t < 216);
    if (is_d4) {
        int g = (t - 128) + 2; o4 = g / 15; l4 = g % 15;
        #pragma unroll
        for (int i = 0; i < 14; i++)
            #pragma unroll
            for (int h = 0; h < 3; h++)
                w4[i * 3 + h] = d4w[i * 18 + o4 * 3 + h];
        b4 = d4b[o4];
    }
    // warp-0 per-lane middle weights (preselected / zero-masked)
    float wc2[19];          // conv2 (lanes 0..11)
    if (t < 12) {
        int o = t / 3;
        const float2* c2w2 = reinterpret_cast<const float2*>(c2w + o * 18);
        #pragma unroll
        for (int i = 0; i < 9; i++) {
            float2 q = c2w2[i];
            wc2[i * 2 + 0] = q.x; wc2[i * 2 + 1] = q.y;
        }
        wc2[18] = c2b[o];
    }
    float wd2[13];          // dec2 (lanes 0..9)
    if (t < 10) {
        int o = t / 5, l = t % 5;
        #pragma unroll
        for (int i = 0; i < 4; i++)
            #pragma unroll
            for (int p = 0; p < 3; p++) {
                int h = l - p;
                wd2[i * 3 + p] = (h >= 0 && h < 3) ? d2w[(i * 2 + o) * 3 + h] : 0.0f;
            }
        wd2[12] = d2b[o];
    }
    float wd3[7];           // dec3 (lanes 0..29)
    if (t < 30) {
        int o = t / 15, l = t % 15;
        #pragma unroll
        for (int i = 0; i < 2; i++)
            #pragma unroll
            for (int h = 0; h < 3; h++) {
                int p = l - h;
                wd3[i * 3 + h] = (p >= 0 && p < 13) ? d3w[(i * 2 + o) * 3 + h] : 0.0f;
            }
        wd3[6] = d3b[o];
    }
    // psi + obsd tail on warp-0 lane 31 (hidden under warp 0's NBAR1 wait)
    float psi_v = 0.0f, obsd_v = 0.0f;
    if (t == 31) {
        float qw = x[3], qx = x[4], qy = x[5], qz = x[6];
        psi_v  = fatan2(qz, qw) - fatan2(-qx, qy);
        obsd_v = x[100];
    }
    // shared bank for remaining tiny stages (loaded by warps 1-6)
    if (t >= 32) {
        int u = t - 32;  // 0..191
        #define CP(off, src, n) for (int i = u; i < (n); i += 192) W[(off) + i] = (src)[i];
        CP(C3W, c3w, 48)  CP(C3B, c3b, 4)
        CP(E1W, e1w, 24)  CP(E1B, e1b, 4)
        CP(E2W, e2w, 16)  CP(E2B, e2b, 4)
        CP(D1W, d1w, 48)  CP(D1B, d1b, 4)
        #undef CP
    }
    __syncthreads();   // ---- b1: jcat + W bank ready ----

    if (t < 32) {
        // ======== warp 0: prefetch middle weights (hidden under conv1) ======
        const int oc = t & 3;
        const int rd = (t < 12) ? t : 0;
        const int od = rd / 3, ld = rd % 3;
        float wc3[12], we1[6], we2[4], wd1[4];
        #pragma unroll
        for (int i = 0; i < 4; i++)
            #pragma unroll
            for (int h = 0; h < 3; h++)
                wc3[i * 3 + h] = W[C3W + (oc * 4 + i) * 3 + h];
        float bc3 = W[C3B + oc];
        #pragma unroll
        for (int i = 0; i < 6; i++) we1[i] = W[E1W + oc * 6 + i];
        float be1 = W[E1B + oc];
        #pragma unroll
        for (int i = 0; i < 4; i++) we2[i] = W[E2W + oc * 4 + i];
        float be2 = W[E2B + oc];
        #pragma unroll
        for (int i = 0; i < 4; i++) wd1[i] = W[D1W + (i * 4 + od) * 3 + ld];
        float bd1 = W[D1B + od];

        NBAR(1, 128);   // ---- fm1 ready (warp 0 + warps 1-3) ----

        // ======== middle: register-resident, shuffle-chained ================
        const unsigned FULL = 0xffffffffu;

        // pool 13 -> 5 (lanes 0..29: o*5+p)
        int rr = (t < 30) ? t : 0;
        int po = rr / 5, pp = rr % 5;
        int S = (pp * 13) / 5;
        int sz4 = (((pp + 1) * 13 + 4) / 5 - S) == 4;
        float v3 = fm1[po][S + 3];
        float vp = fm1[po][S] + fm1[po][S + 1] + fm1[po][S + 2] + (sz4 ? v3 : 0.0f);
        vp *= sz4 ? 0.25f : (1.0f / 3.0f);

        // conv2 (lanes 0..11)
        int r2 = (t < 12) ? t : 0;
        int l2 = r2 % 3;
        float a0 = wc2[18], a1 = 0.0f;
        #pragma unroll
        for (int i = 0; i < 6; i++) {
            float v0 = __shfl_sync(FULL, vp, i * 5 + l2 + 0);
            float v1 = __shfl_sync(FULL, vp, i * 5 + l2 + 1);
            float v2 = __shfl_sync(FULL, vp, i * 5 + l2 + 2);
            a0 = fmaf(wc2[i * 3 + 0], v0, a0);
            a1 = fmaf(wc2[i * 3 + 1], v1, a1);
            a0 = fmaf(wc2[i * 3 + 2], v2, a0);
        }
        float fm2v = htanh(a0 + a1);

        // conv3 (lanes 0..3)
        float c0 = bc3, c1 = 0.0f;
        #pragma unroll
        for (int i = 0; i < 4; i++)
            #pragma unroll
            for (int h = 0; h < 3; h++) {
                float v = __shfl_sync(FULL, fm2v, i * 3 + h);
                if (h & 1) c1 = fmaf(wc3[i * 3 + h], v, c1);
                else       c0 = fmaf(wc3[i * 3 + h], v, c0);
            }
        float c3v = htanh(c0 + c1);

        // emb1 (lanes 0..3, 6->4); psi/obsd shuffled from lane 31
        float psi_b  = __shfl_sync(FULL, psi_v, 31);
        float obsd_b = __shfl_sync(FULL, obsd_v, 31);
        float e0 = be1, e1a = 0.0f;
        #pragma unroll
        for (int i = 0; i < 4; i++) {
            float v = __shfl_sync(FULL, c3v, i);
            if (i & 1) e1a = fmaf(we1[i], v, e1a);
            else       e0  = fmaf(we1[i], v, e0);
        }
        e0  = fmaf(we1[4], psi_b, e0);
        e1a = fmaf(we1[5], obsd_b, e1a);
        float e1v = htanh(e0 + e1a);

        // emb2 (lanes 0..3, 4->4)
        float f0 = be2, f1 = 0.0f;
        #pragma unroll
        for (int i = 0; i < 4; i++) {
            float v = __shfl_sync(FULL, e1v, i);
            if (i & 1) f1 = fmaf(we2[i], v, f1);
            else       f0 = fmaf(we2[i], v, f0);
        }
        float e2v = htanh(f0 + f1);

        // dec1 (lanes 0..11)
        float g0 = bd1, g1 = 0.0f;
        #pragma unroll
        for (int i = 0; i < 4; i++) {
            float v = __shfl_sync(FULL, e2v, i);
            if (i & 1) g1 = fmaf(wd1[i], v, g1);
            else       g0 = fmaf(wd1[i], v, g0);
        }
        float d1v = htanh(g0 + g1);

        // dec2 (lanes 0..9)
        float h0 = wd2[12], h1 = 0.0f;
        #pragma unroll
        for (int i = 0; i < 4; i++)
            #pragma unroll
            for (int p = 0; p < 3; p++) {
                float v = __shfl_sync(FULL, d1v, i * 3 + p);
                if (p & 1) h1 = fmaf(wd2[i * 3 + p], v, h1);
                else       h0 = fmaf(wd2[i * 3 + p], v, h0);
            }
        float d2v = htanh(h0 + h1);

        // dec3 + fused upsample (lanes 0..29) -> cat rows 0,1
        int r3 = (t < 30) ? t : 0;
        int o3 = r3 / 15, l3 = r3 % 15;
        float k0 = wd3[6], k1 = 0.0f;
        #pragma unroll
        for (int i = 0; i < 2; i++)
            #pragma unroll
            for (int h = 0; h < 3; h++) {
                int p = l3 - h;
                int pc = p < 0 ? 0 : (p > 12 ? 12 : p);
                int q = (pc * 5) / 13;                 // UP_IDX
                float v = __shfl_sync(FULL, d2v, i * 5 + q);
                if (h & 1) k1 = fmaf(wd3[i * 3 + h], v, k1);
                else       k0 = fmaf(wd3[i * 3 + h], v, k0);
            }
        if (t < 30) cat[o3][1 + l3] = htanh(k0 + k1);

        NBAR(2, 128);   // ---- dc3 ready (warp 0 + warps 4-6) ----
    } else if (t < 128) {
        // ======== warps 1-3: conv1 (12,15) k=3 -> (6,13), tanh ==============
        if (is_c1) {
            float s0 = b1, s1 = 0.0f, s2 = 0.0f;
            #pragma unroll
            for (int i = 0; i < 12; i++) {
                s0 = fmaf(w1[i * 3 + 0], cat[2 + i][1 + l1 + 0], s0);
                s1 = fmaf(w1[i * 3 + 1], cat[2 + i][1 + l1 + 1], s1);
                s2 = fmaf(w1[i * 3 + 2], cat[2 + i][1 + l1 + 2], s2);
            }
            fm1[o1][l1] = htanh(s0 + s1 + s2);
        }
        NBAR(1, 128);   // fm1 ready
    } else {
        // ======== warps 4-6: dec4 jcat-partial, then wait for dc3 ===========
        float partial = 0.0f;
        if (is_d4) {
            float s0 = b4, s1 = 0.0f, s2 = 0.0f;
            #pragma unroll
            for (int h = 0; h < 3; h++) {
                int p = l4 - h + 2;   // [0..16], pads zero
                #pragma unroll
                for (int i = 2; i < 14; i++) {
                    float v = cat[i][p];
                    if (i % 3 == 0)      s0 = fmaf(w4[i * 3 + h], v, s0);
                    else if (i % 3 == 1) s1 = fmaf(w4[i * 3 + h], v, s1);
                    else                 s2 = fmaf(w4[i * 3 + h], v, s2);
                }
            }
            partial = s0 + s1 + s2;
        }
        NBAR(2, 128);   // dc3 ready

        if (is_d4) {
            float s = partial;
            #pragma unroll
            for (int h = 0; h < 3; h++) {
                int p = l4 - h + 2;
                s = fmaf(w4[0 * 3 + h], cat[0][p], s);
                s = fmaf(w4[1 * 3 + h], cat[1][p], s);
            }
            out[t - 128] = s;
        }
    }
}

extern "C" void kernel_launch(void* const* d_in, const int* in_sizes, int n_in,
                              void* d_out, int out_size) {
    (void)in_sizes; (void)n_in; (void)out_size;
    conv_policy_kernel<<<1, NT>>>(
        (const float*)d_in[0],
        (const float*)d_in[1],  (const float*)d_in[2],
        (const float*)d_in[3],  (const float*)d_in[4],
        (const float*)d_in[5],  (const float*)d_in[6],
        (const float*)d_in[7],  (const float*)d_in[8],
        (const float*)d_in[9],  (const float*)d_in[10],
        (const float*)d_in[11], (const float*)d_in[12],
        (const float*)d_in[13], (const float*)d_in[14],
        (const float*)d_in[15], (const float*)d_in[16],
        (const float*)d_in[17], (const float*)d_in[18],
        (float*)d_out);
}